// round 8
// baseline (speedup 1.0000x reference)
#include <cuda_runtime.h>
#include <cuda_fp16.h>
#include <cstdint>
#include <math.h>

// DeformAttn via ldmatrix + mma.sync (m16n8k16 fp16, fp32 accum) — base sm_103 ISA.
// Round 8: warp tile m16 x n32 (8 warps = 128 out-ch, D_TILE=32).
// Wk/Wv A-fragments PERSIST in registers across all 9 samples (64 regs);
// hot-loop LDS is B-fragments only (16 ldsm/warp/sample, was 48).
// W pre-swizzled fp16 scratch (prep kernel) + cp.async staging.

namespace {
constexpr int Bn = 4, Cn = 128, Sn = 9, Dn = 16384;
constexpr int D_TILE = 32;
constexpr int NT = 256;
constexpr float ATT_SCALE = 0.25f;

constexpr int SM_WQ = 0;            // 3 x 32KB swizzled fp16 W
constexpr int SM_WK = 32768;
constexpr int SM_WV = 65536;
constexpr int SM_X  = 98304;        // 2 x-slice buffers [128c x 32d] fp16, 8KB each
constexpr int SM_TOTAL = 114688;
}

__device__ __align__(16) char g_wh[3 * 32768];

__device__ __forceinline__ uint32_t smem_u32(const void* p) {
    uint32_t a;
    asm("{ .reg .u64 t; cvta.to.shared.u64 t, %1; cvt.u32.u64 %0, t; }" : "=r"(a) : "l"(p));
    return a;
}
// W rows: 256B (128 halfwords), 16B chunks XOR-swizzled by row&7
__device__ __forceinline__ uint32_t swzW(int row, int colh) {
    int chunk = (colh >> 3) ^ (row & 7);
    return (uint32_t)(row * 256 + chunk * 16 + (colh & 7) * 2);
}
// x slice rows: 64B (32 halfwords), 16B chunks XOR-swizzled by (row>>1)&3
__device__ __forceinline__ uint32_t swzX(int row, int colh) {
    int chunk = ((colh >> 3) & 3) ^ ((row >> 1) & 3);
    return (uint32_t)(row * 64 + chunk * 16 + (colh & 7) * 2);
}
__device__ __forceinline__ void ldsm4(uint32_t r[4], uint32_t addr) {
    asm volatile("ldmatrix.sync.aligned.m8n8.x4.shared.b16 {%0,%1,%2,%3}, [%4];"
                 : "=r"(r[0]), "=r"(r[1]), "=r"(r[2]), "=r"(r[3]) : "r"(addr));
}
__device__ __forceinline__ void ldsm4t(uint32_t r[4], uint32_t addr) {
    asm volatile("ldmatrix.sync.aligned.m8n8.x4.trans.shared.b16 {%0,%1,%2,%3}, [%4];"
                 : "=r"(r[0]), "=r"(r[1]), "=r"(r[2]), "=r"(r[3]) : "r"(addr));
}
__device__ __forceinline__ void mma16816(float d[4], const uint32_t a[4], const uint32_t b[2]) {
    asm volatile(
        "mma.sync.aligned.m16n8k16.row.col.f32.f16.f16.f32 "
        "{%0,%1,%2,%3},{%4,%5,%6,%7},{%8,%9},{%0,%1,%2,%3};"
        : "+f"(d[0]), "+f"(d[1]), "+f"(d[2]), "+f"(d[3])
        : "r"(a[0]), "r"(a[1]), "r"(a[2]), "r"(a[3]), "r"(b[0]), "r"(b[1]));
}

// ---- prep kernel: W fp32 [o][c] -> swizzled fp16 scratch ----
__global__ void prep_w(const float* __restrict__ Wq, const float* __restrict__ Wk,
                       const float* __restrict__ Wv) {
    const int t = blockIdx.x * 256 + threadIdx.x;   // 0..12287
    const int w = t >> 12;
    const int rem = t & 4095;
    const int o = rem >> 5, f4 = rem & 31;
    const float* W = (w == 0) ? Wq : (w == 1) ? Wk : Wv;
    const float4 v = *reinterpret_cast<const float4*>(W + o * 128 + f4 * 4);
    char* dst = g_wh + w * 32768 + swzW(o, f4 * 4);
    *reinterpret_cast<__half2*>(dst)     = __floats2half2_rn(v.x, v.y);
    *reinterpret_cast<__half2*>(dst + 4) = __floats2half2_rn(v.z, v.w);
}

// ---- x slice staging: 256 threads stage [128c x 32d] fp32 -> fp16, 4 float4 each ----
__device__ __forceinline__ void pf_load(float4 pf[4], const float* __restrict__ src,
                                        long cstride, int tid) {
#pragma unroll
    for (int i = 0; i < 4; i++) {
        const int g = i * 256 + tid;
        const int c = g >> 3, d4 = (g & 7) * 4;
        pf[i] = *reinterpret_cast<const float4*>(src + (long)c * cstride + d4);
    }
}
__device__ __forceinline__ void pf_store(char* xb, const float4 pf[4], int tid) {
#pragma unroll
    for (int i = 0; i < 4; i++) {
        const int g = i * 256 + tid;
        const int c = g >> 3, d4 = (g & 7) * 4;
        const uint32_t off = swzX(c, d4);
        *reinterpret_cast<__half2*>(xb + off)     = __floats2half2_rn(pf[i].x, pf[i].y);
        *reinterpret_cast<__half2*>(xb + off + 4) = __floats2half2_rn(pf[i].z, pf[i].w);
    }
}

__global__ void __launch_bounds__(NT, 1)
deform_attn_hmma(const float* __restrict__ q,  const float* __restrict__ kv,
                 const float* __restrict__ bq, const float* __restrict__ bv,
                 float* __restrict__ out)
{
    extern __shared__ char smem[];
    const uint32_t sb = smem_u32(smem);
    const int tid = threadIdx.x, lane = tid & 31, wid = tid >> 5;
    const int b = blockIdx.y;
    const int dt = blockIdx.x * D_TILE;

    // A-fragment ldsm address (this warp's 16 rows = one head)
    const int a_row  = wid * 16 + (lane & 7) + ((lane >> 3) & 1) * 8;
    const int a_colq = (lane >> 4) * 8;
    // B-fragment ldsm4t base indices
    const int tl = lane >> 3;
    const int b_crem = (tl & 1) * 8 + (lane & 7);
    const int b_drem = (tl >> 1) * 8;

    char* xs0 = smem + SM_X;
    char* xs1 = smem + SM_X + 8192;
    const uint32_t xb0 = sb + SM_X;
    const uint32_t xb1 = xb0 + 8192;

    // ---- stage all three W via identity cp.async from pre-swizzled scratch ----
#pragma unroll
    for (int i = 0; i < 24; i++) {
        const uint32_t dst = sb + (uint32_t)(tid * 16 + i * 4096);
        const char* src = g_wh + tid * 16 + i * 4096;
        asm volatile("cp.async.cg.shared.global [%0], [%1], 16;" :: "r"(dst), "l"(src));
    }
    asm volatile("cp.async.commit_group;" ::: "memory");

    // ---- stage q slice into buf0 ----
    {
        float4 pf[4];
        pf_load(pf, q + (long)b * Cn * Dn + dt, (long)Dn, tid);
        pf_store(xs0, pf, tid);
    }
    asm volatile("cp.async.wait_group 0;" ::: "memory");
    __syncthreads();

    // ---- persistent A fragments for Wk, Wv (32 regs each) ----
    uint32_t akK[8][4], akV[8][4];
#pragma unroll
    for (int ks = 0; ks < 8; ks++) {
        const int colh = ks * 16 + a_colq;
        ldsm4(akK[ks], sb + SM_WK + swzW(a_row, colh));
        ldsm4(akV[ks], sb + SM_WV + swzW(a_row, colh));
    }

    // ---- Q projection: m16 x n32 ----
    float qp[4][4];
#pragma unroll
    for (int n = 0; n < 4; n++) qp[n][0] = qp[n][1] = qp[n][2] = qp[n][3] = 0.0f;
#pragma unroll
    for (int ks = 0; ks < 8; ks++) {
        uint32_t aq[4];
        ldsm4(aq, sb + SM_WQ + swzW(a_row, ks * 16 + a_colq));
        const int c = ks * 16 + b_crem;
        uint32_t r4a[4], r4b[4];
        ldsm4t(r4a, xb0 + swzX(c, b_drem));
        ldsm4t(r4b, xb0 + swzX(c, 16 + b_drem));
        uint32_t f0[2] = {r4a[0], r4a[1]}, f1[2] = {r4a[2], r4a[3]};
        uint32_t f2[2] = {r4b[0], r4b[1]}, f3[2] = {r4b[2], r4b[3]};
        mma16816(qp[0], aq, f0);
        mma16816(qp[1], aq, f1);
        mma16816(qp[2], aq, f2);
        mma16816(qp[3], aq, f3);
    }

    const int r0 = wid * 16 + (lane >> 2);
    {
        const float b0 = bq[r0], b1 = bq[r0 + 8];
#pragma unroll
        for (int n = 0; n < 4; n++) {
            qp[n][0] += b0; qp[n][1] += b0; qp[n][2] += b1; qp[n][3] += b1;
        }
    }

    float acc[4][4], den[4][2];
#pragma unroll
    for (int n = 0; n < 4; n++) {
        acc[n][0] = acc[n][1] = acc[n][2] = acc[n][3] = 0.0f;
        den[n][0] = den[n][1] = 0.0f;
    }

    // ---- stage kv sample 0 into buf0 ----
    __syncthreads();   // Q-proj readers done with buf0
    {
        float4 pf[4];
        pf_load(pf, kv + (long)(b * Cn) * Sn * Dn + dt, (long)Sn * Dn, tid);
        pf_store(xs0, pf, tid);
    }
    __syncthreads();

    float4 pf[4];
    for (int s = 0; s < Sn; s++) {
        const uint32_t xb = (s & 1) ? xb1 : xb0;
        char* nxt = ((s + 1) & 1) ? xs1 : xs0;

        if (s + 1 < Sn)
            pf_load(pf, kv + ((long)(b * Cn) * Sn + (s + 1)) * Dn + dt, (long)Sn * Dn, tid);

        // fused K+V: B-frags only from smem, A persistent in registers
        float kp[4][4], vp[4][4];
#pragma unroll
        for (int n = 0; n < 4; n++) {
            kp[n][0] = kp[n][1] = kp[n][2] = kp[n][3] = 0.0f;
            vp[n][0] = vp[n][1] = vp[n][2] = vp[n][3] = 0.0f;
        }
#pragma unroll
        for (int ks = 0; ks < 8; ks++) {
            const int c = ks * 16 + b_crem;
            uint32_t r4a[4], r4b[4];
            ldsm4t(r4a, xb + swzX(c, b_drem));
            ldsm4t(r4b, xb + swzX(c, 16 + b_drem));
            uint32_t f0[2] = {r4a[0], r4a[1]}, f1[2] = {r4a[2], r4a[3]};
            uint32_t f2[2] = {r4b[0], r4b[1]}, f3[2] = {r4b[2], r4b[3]};
            mma16816(kp[0], akK[ks], f0);
            mma16816(kp[1], akK[ks], f1);
            mma16816(kp[2], akK[ks], f2);
            mma16816(kp[3], akK[ks], f3);
            mma16816(vp[0], akV[ks], f0);
            mma16816(vp[1], akV[ks], f1);
            mma16816(vp[2], akV[ks], f2);
            mma16816(vp[3], akV[ks], f3);
        }

        // softmax over this warp's 16-row head + weighted V accumulate
#pragma unroll
        for (int n = 0; n < 4; n++) {
            float pe = qp[n][0] * kp[n][0] + qp[n][2] * kp[n][2];
            float po = qp[n][1] * kp[n][1] + qp[n][3] * kp[n][3];
            pe += __shfl_xor_sync(0xffffffffu, pe, 4);
            pe += __shfl_xor_sync(0xffffffffu, pe, 8);
            pe += __shfl_xor_sync(0xffffffffu, pe, 16);
            po += __shfl_xor_sync(0xffffffffu, po, 4);
            po += __shfl_xor_sync(0xffffffffu, po, 8);
            po += __shfl_xor_sync(0xffffffffu, po, 16);
            const float we = __expf(ATT_SCALE * pe);
            const float wo = __expf(ATT_SCALE * po);
            den[n][0] += we; den[n][1] += wo;
            acc[n][0] = fmaf(we, vp[n][0], acc[n][0]);
            acc[n][1] = fmaf(wo, vp[n][1], acc[n][1]);
            acc[n][2] = fmaf(we, vp[n][2], acc[n][2]);
            acc[n][3] = fmaf(wo, vp[n][3], acc[n][3]);
        }

        // write s+1 into the buffer whose readers finished before the LAST barrier
        if (s + 1 < Sn) pf_store(nxt, pf, tid);
        __syncthreads();
    }

    // ---- output: out = acc/den + bv ----
    {
        const float bv0 = bv[r0], bv1 = bv[r0 + 8];
#pragma unroll
        for (int n = 0; n < 4; n++) {
            float* dst = out + ((long)(b * Cn + r0)) * Dn + dt + n * 8 + (lane & 3) * 2;
            const float de = den[n][0], dz = den[n][1];
            float2 v0 = make_float2(acc[n][0] / de + bv0, acc[n][1] / dz + bv0);
            float2 v1 = make_float2(acc[n][2] / de + bv1, acc[n][3] / dz + bv1);
            *reinterpret_cast<float2*>(dst) = v0;
            *reinterpret_cast<float2*>(dst + (long)8 * Dn) = v1;
        }
    }
}

extern "C" void kernel_launch(void* const* d_in, const int* in_sizes, int n_in,
                              void* d_out, int out_size) {
    const float* q  = (const float*)d_in[0];
    const float* kv = (const float*)d_in[1];
    const float* Wq = (const float*)d_in[2];
    const float* bq = (const float*)d_in[3];
    const float* Wk = (const float*)d_in[4];
    // d_in[5] = bk: unused (softmax-invariant)
    const float* Wv = (const float*)d_in[6];
    const float* bv = (const float*)d_in[7];
    float* out = (float*)d_out;

    prep_w<<<48, 256>>>(Wq, Wk, Wv);

    cudaFuncSetAttribute(deform_attn_hmma,
                         cudaFuncAttributeMaxDynamicSharedMemorySize, SM_TOTAL);
    dim3 grid(Dn / D_TILE, Bn);   // 512 x 4 = 2048 blocks
    deform_attn_hmma<<<grid, NT, SM_TOTAL>>>(q, kv, bq, bv, out);
}